// round 8
// baseline (speedup 1.0000x reference)
#include <cuda_runtime.h>
#include <math.h>

// Problem constants
#define NTOK   32768      // B*H*W
#define KCB    1024
#define DIM    64
#define HWSZ   1024
#define QELEMS 2097152    // NTOK*DIM
#define INVEPS 20.0f
#define NSTEPS 10
#define NFIN   256        // k_fin blocks / mse partials
#define WIN    3          // OT stencil half-width (validated: identical to exact)

// ---------------- scratch (device globals) ----------------------------------
__device__ float g_cd[2 * NTOK];      // candidate distance per half
__device__ int   g_ci[2 * NTOK];      // candidate index per half
__device__ int   g_hist[KCB];         // zero at load; k_ot re-zeroes after use
__device__ float g_msepart[NFIN];

// ---------------- K1: split-K distances + argmin candidates -----------------
// 256 CTAs (2/SM, single wave), 256 thr/CTA, 1 token/thread -> 4 warps/SMSP.
// FMA2 lane assignment identical to R7 token-0 path (bit-exact distances).
__global__ void __launch_bounds__(256, 2) k_main(const float* __restrict__ x,
                                                 const float* __restrict__ cb) {
    const int tid   = threadIdx.x;
    const int group = blockIdx.x >> 1;
    const int half  = blockIdx.x & 1;
    const int n     = group * 256 + tid;
    const int b     = n >> 10, hw = n & 1023;

    const float* xb = x + (size_t)b * (DIM * HWSZ) + hw;
    unsigned long long xp[32];
    float xsq = 0.0f;
    #pragma unroll
    for (int t = 0; t < 32; t++) {
        float e0 = xb[(2 * t) * HWSZ];
        float e1 = xb[(2 * t + 1) * HWSZ];
        xsq = fmaf(e0, e0, xsq);
        xsq = fmaf(e1, e1, xsq);
        asm("mov.b64 %0, {%1, %2};" : "=l"(xp[t]) : "f"(e0), "f"(e1));
    }

    __shared__ float s_code[128 * DIM];   // 32 KB chunk
    __shared__ float s_csq[128];

    float best = 3.4e38f;
    int   bj   = half * 512;

    const int cbase = half * 512;
    for (int c0i = cbase; c0i < cbase + 512; c0i += 128) {
        __syncthreads();
        const float4* src4 = (const float4*)(cb + (size_t)c0i * DIM);
        float4* dst4 = (float4*)s_code;
        #pragma unroll
        for (int t = 0; t < 8; t++) dst4[tid + 256 * t] = __ldg(src4 + tid + 256 * t);
        __syncthreads();
        if (tid < 128) {   // |c|^2 row tid, same sequential fmaf order as before
            const float4* r = (const float4*)(s_code + tid * DIM);
            float s = 0.0f;
            #pragma unroll
            for (int t = 0; t < 16; t++) {
                float4 c = r[t];
                s = fmaf(c.x, c.x, s); s = fmaf(c.y, c.y, s);
                s = fmaf(c.z, c.z, s); s = fmaf(c.w, c.w, s);
            }
            s_csq[tid] = s;
        }
        __syncthreads();

        #pragma unroll 4
        for (int j = 0; j < 128; j++) {
            const ulonglong2* cp = (const ulonglong2*)(s_code + j * DIM);
            unsigned long long p0 = 0ull, p1 = 0ull, p2 = 0ull, p3 = 0ull;
            #pragma unroll
            for (int t = 0; t < 16; t += 2) {
                ulonglong2 cA = cp[t];
                ulonglong2 cB = cp[t + 1];
                asm("fma.rn.f32x2 %0, %1, %2, %0;" : "+l"(p0) : "l"(xp[2 * t + 0]), "l"(cA.x));
                asm("fma.rn.f32x2 %0, %1, %2, %0;" : "+l"(p1) : "l"(xp[2 * t + 1]), "l"(cA.y));
                asm("fma.rn.f32x2 %0, %1, %2, %0;" : "+l"(p2) : "l"(xp[2 * t + 2]), "l"(cB.x));
                asm("fma.rn.f32x2 %0, %1, %2, %0;" : "+l"(p3) : "l"(xp[2 * t + 3]), "l"(cB.y));
            }
            unsigned long long u01, u23, uu;
            asm("add.rn.f32x2 %0, %1, %2;" : "=l"(u01) : "l"(p0), "l"(p1));
            asm("add.rn.f32x2 %0, %1, %2;" : "=l"(u23) : "l"(p2), "l"(p3));
            asm("add.rn.f32x2 %0, %1, %2;" : "=l"(uu)  : "l"(u01), "l"(u23));
            float lo, hi;
            asm("mov.b64 {%0, %1}, %2;" : "=f"(lo), "=f"(hi) : "l"(uu));
            float dot = lo + hi;
            float cs = s_csq[j];
            // faithful: (|x|^2 + |c|^2) - 2*dot, no FMA contraction
            float d = __fsub_rn(__fadd_rn(xsq, cs), __fmul_rn(2.0f, dot));
            if (d < best) { best = d; bj = c0i + j; }   // strict < = first-min
        }
    }

    g_cd[half * NTOK + n] = best;
    g_ci[half * NTOK + n] = bj;
}

// ---------------- K2: merge halves + quantized + mse + histogram ------------
__global__ void __launch_bounds__(128) k_fin(const float* __restrict__ x,
                                             const float* __restrict__ cb,
                                             float* __restrict__ out) {
    const int tid = threadIdx.x;
    const int n   = blockIdx.x * 128 + tid;
    const int b   = n >> 10, hw = n & 1023;

    __shared__ int s_hist[KCB];
    #pragma unroll
    for (int k = 0; k < 8; k++) s_hist[tid + 128 * k] = 0;

    // merge: lower half wins ties (first-min over full K)
    float dA = g_cd[n];
    float dB = g_cd[NTOK + n];
    int   iA = g_ci[n];
    int   iB = g_ci[NTOK + n];
    int bestj = (dB < dA) ? iB : iA;

    __syncthreads();
    atomicAdd(&s_hist[bestj], 1);

    // quantized output + mse
    const float* xb = x + (size_t)b * (DIM * HWSZ) + hw;
    const float4* q4 = (const float4*)(cb + (size_t)bestj * DIM);
    float* ob = out + (size_t)b * (DIM * HWSZ) + hw;
    float ms = 0.0f;
    #pragma unroll
    for (int t = 0; t < 16; t++) {
        float4 qv = __ldg(q4 + t);
        float x0 = xb[(4 * t + 0) * HWSZ];
        float x1 = xb[(4 * t + 1) * HWSZ];
        float x2 = xb[(4 * t + 2) * HWSZ];
        float x3 = xb[(4 * t + 3) * HWSZ];
        float d0 = __fsub_rn(qv.x, x0), d1 = __fsub_rn(qv.y, x1);
        float d2 = __fsub_rn(qv.z, x2), d3 = __fsub_rn(qv.w, x3);
        ms = fmaf(d0, d0, ms); ms = fmaf(d1, d1, ms);
        ms = fmaf(d2, d2, ms); ms = fmaf(d3, d3, ms);
        ob[(4 * t + 0) * HWSZ] = __fadd_rn(x0, d0);
        ob[(4 * t + 1) * HWSZ] = __fadd_rn(x1, d1);
        ob[(4 * t + 2) * HWSZ] = __fadd_rn(x2, d2);
        ob[(4 * t + 3) * HWSZ] = __fadd_rn(x3, d3);
    }
    #pragma unroll
    for (int o = 16; o > 0; o >>= 1) ms += __shfl_xor_sync(0xffffffffu, ms, o);
    __shared__ float s_ms[4];
    if ((tid & 31) == 0) s_ms[tid >> 5] = ms;
    __syncthreads();
    if (tid == 0) g_msepart[blockIdx.x] = (s_ms[0] + s_ms[1]) + (s_ms[2] + s_ms[3]);

    // sparse histogram flush (int atomics: deterministic)
    #pragma unroll
    for (int k = 0; k < 8; k++) {
        int v = s_hist[tid + 128 * k];
        if (v) atomicAdd(&g_hist[tid + 128 * k], v);
    }
}

// ---------------- block-wide sum (1024 threads) -----------------------------
__device__ __forceinline__ float bsum(float v, float* sh32, int tid) {
    #pragma unroll
    for (int o = 16; o > 0; o >>= 1) v += __shfl_xor_sync(0xffffffffu, v, o);
    if ((tid & 31) == 0) sh32[tid >> 5] = v;
    __syncthreads();
    if (tid < 32) {
        float w = sh32[tid];
        #pragma unroll
        for (int o = 16; o > 0; o >>= 1) w += __shfl_xor_sync(0xffffffffu, w, o);
        if (tid == 0) sh32[0] = w;
    }
    __syncthreads();
    float r = sh32[0];
    __syncthreads();
    return r;
}

// ---------------- K3: target + stats + OT dual + loss (one CTA) -------------
__global__ void __launch_bounds__(1024) k_ot(float* __restrict__ out) {
    const int j = threadIdx.x;
    __shared__ float sh32[32];
    __shared__ float s_lt[KCB];
    __shared__ float s_phi[KCB];
    __shared__ float s_lse[KCB];
    __shared__ float s_src[KCB];

    // consume histogram, restore load-time-zero invariant for next replay
    const int hj = g_hist[j];
    g_hist[j] = 0;

    // gaussian target (faithful: _gaussian_target then _norm_prob)
    float z = ((float)j - 511.5f) / (1024.0f / 6.0f);
    float t = expf(-0.5f * z * z);
    float sum1 = bsum(t, sh32, j);
    float t1 = t / fmaxf(sum1, 1e-12f);
    float t2 = fmaxf(t1, 1e-12f);
    float sum2 = bsum(t2, sh32, j);
    const float tgt = t2 / sum2;
    const float lt  = logf(fmaxf(tgt, 1e-12f));
    s_lt[j] = lt;

    // perplexity
    float avg = (float)hj / (float)NTOK;
    float ent = bsum(avg * logf(avg + 1e-10f), sh32, j);
    if (j == 0) out[QELEMS + 1] = expf(-ent);

    // src weights: norm_prob(hard_hist), then norm_prob again (dual_obj)
    float p1 = fmaxf(avg, 1e-12f);
    float s1 = bsum(p1, sh32, j);
    float p2 = fmaxf(p1 / s1, 1e-12f);
    float s2 = bsum(p2, sh32, j);
    const float src = p2 / s2;
    s_src[j] = src;

    // total mse
    const float mse_tot = bsum((j < NFIN) ? g_msepart[j] : 0.0f, sh32, j);

    // dual ascent loop (compile-time +/-WIN stencil)
    float phi = 0.0f;
    s_phi[j] = 0.0f;
    __syncthreads();

    float lse = 0.0f;
    for (int step = 0; step <= NSTEPS; step++) {
        float a[2 * WIN + 1];
        float m = -3.4e38f;
        #pragma unroll
        for (int u = -WIN; u <= WIN; u++) {
            int jj = j + u;
            bool valid = (jj >= 0) && (jj < KCB);
            int jc = valid ? jj : j;
            float v = s_lt[jc] + fmaf(s_phi[jc], INVEPS, -(float)(u < 0 ? -u : u) * INVEPS);
            v = valid ? v : -3.0e38f;
            a[u + WIN] = v;
            m = fmaxf(m, v);
        }
        float s = 0.0f;
        #pragma unroll
        for (int u = 0; u < 2 * WIN + 1; u++) s += expf(a[u] - m);
        lse = m + logf(s);
        s_lse[j] = lse;
        __syncthreads();
        if (step == NSTEPS) break;
        float mar = 0.0f;
        #pragma unroll
        for (int u = -WIN; u <= WIN; u++) {
            int i = j + u;
            bool valid = (i >= 0) && (i < KCB);
            int ic = valid ? i : j;
            float v = lt + fmaf(phi, INVEPS, -(float)(u < 0 ? -u : u) * INVEPS) - s_lse[ic];
            float c = s_src[ic] * expf(v);
            mar += valid ? c : 0.0f;
        }
        phi = phi + 0.5f * (tgt - mar);
        __syncthreads();
        s_phi[j] = phi;
        __syncthreads();
    }

    // dual objective + loss
    float t1s = bsum(src * (-0.05f * lse), sh32, j);
    float t2s = bsum(tgt * phi, sh32, j);
    if (j == 0) {
        float obj = t1s + t2s;                        // ot_loss (OT_W = 1)
        float m = mse_tot / (float)QELEMS;            // codebook == commit value
        out[QELEMS] = (m + 0.25f * m) + obj;          // loss
    }
}

// ---------------- launch ----------------------------------------------------
extern "C" void kernel_launch(void* const* d_in, const int* in_sizes, int n_in,
                              void* d_out, int out_size) {
    const float* x  = (const float*)d_in[0];   // inputs [32,64,32,32]
    const float* cb = (const float*)d_in[1];   // codebook [1024,64]
    if (n_in >= 2 && in_sizes[0] == KCB * DIM && in_sizes[1] == QELEMS) {
        x = (const float*)d_in[1]; cb = (const float*)d_in[0];
    }
    float* out = (float*)d_out;

    k_main<<<256, 256>>>(x, cb);
    k_fin<<<NFIN, 128>>>(x, cb, out);
    k_ot<<<1, 1024>>>(out);
}

// round 9
// speedup vs baseline: 1.1670x; 1.1670x over previous
#include <cuda_runtime.h>
#include <math.h>

// Problem constants
#define NTOK   32768      // B*H*W
#define KCB    1024
#define DIM    64
#define HWSZ   1024
#define QELEMS 2097152    // NTOK*DIM
#define INVEPS 20.0f
#define NSTEPS 10
#define NFIN   256        // k_fin blocks / mse partials
#define TOKOFF 16384
#define NQ     4          // split-K quarters
#define WIN    3          // OT stencil half-width (validated: identical to exact)

// ---------------- scratch (device globals) ----------------------------------
__device__ float g_cd[NQ * NTOK];     // candidate distance per quarter
__device__ int   g_ci[NQ * NTOK];     // candidate index per quarter
__device__ int   g_hist[KCB];         // zero at load; k_ot re-zeroes after use
__device__ float g_msepart[NFIN];

// ---------------- K1: split-K4 distances + argmin candidates ----------------
// 512 CTAs, 128 thr, 2 tokens/thread, 3 CTAs/SM (reg cap 170) = 3 warps/SMSP.
// Inner loop bit-identical to R7 (T=2 balances FMA vs LDS pipe demand).
__global__ void __launch_bounds__(128, 3) k_main(const float* __restrict__ x,
                                                 const float* __restrict__ cb) {
    const int tid   = threadIdx.x;
    const int group = blockIdx.x >> 2;         // 0..127
    const int q     = blockIdx.x & 3;          // quarter 0..3
    const int n0    = group * 128 + tid;
    const int n1    = n0 + TOKOFF;
    const int b0    = n0 >> 10, hw0 = n0 & 1023;
    const int b1    = n1 >> 10, hw1 = n1 & 1023;

    const float* xb0 = x + (size_t)b0 * (DIM * HWSZ) + hw0;
    const float* xb1 = x + (size_t)b1 * (DIM * HWSZ) + hw1;

    unsigned long long xp0[32], xp1[32];
    float xsq0 = 0.0f, xsq1 = 0.0f;
    #pragma unroll
    for (int t = 0; t < 32; t++) {
        float a0 = xb0[(2 * t) * HWSZ], a1 = xb0[(2 * t + 1) * HWSZ];
        float c0 = xb1[(2 * t) * HWSZ], c1 = xb1[(2 * t + 1) * HWSZ];
        xsq0 = fmaf(a0, a0, xsq0); xsq0 = fmaf(a1, a1, xsq0);
        xsq1 = fmaf(c0, c0, xsq1); xsq1 = fmaf(c1, c1, xsq1);
        asm("mov.b64 %0, {%1, %2};" : "=l"(xp0[t]) : "f"(a0), "f"(a1));
        asm("mov.b64 %0, {%1, %2};" : "=l"(xp1[t]) : "f"(c0), "f"(c1));
    }

    __shared__ float s_code[128 * DIM];   // 32 KB chunk
    __shared__ float s_csq[128];

    float best0 = 3.4e38f, best1 = 3.4e38f;
    int   bj0 = q * 256, bj1 = q * 256;

    const int cbase = q * 256;
    for (int c0i = cbase; c0i < cbase + 256; c0i += 128) {
        __syncthreads();
        const float4* src4 = (const float4*)(cb + (size_t)c0i * DIM);
        float4* dst4 = (float4*)s_code;
        #pragma unroll
        for (int t = 0; t < 16; t++) dst4[tid + 128 * t] = __ldg(src4 + tid + 128 * t);
        __syncthreads();
        {   // in-block |c|^2 for row tid (same sequential fmaf order)
            const float4* r = (const float4*)(s_code + tid * DIM);
            float s = 0.0f;
            #pragma unroll
            for (int t = 0; t < 16; t++) {
                float4 c = r[t];
                s = fmaf(c.x, c.x, s); s = fmaf(c.y, c.y, s);
                s = fmaf(c.z, c.z, s); s = fmaf(c.w, c.w, s);
            }
            s_csq[tid] = s;
        }
        __syncthreads();

        #pragma unroll 2
        for (int j = 0; j < 128; j++) {
            const ulonglong2* cp = (const ulonglong2*)(s_code + j * DIM);
            unsigned long long p0 = 0ull, p1 = 0ull, p2 = 0ull, p3 = 0ull;
            unsigned long long q0 = 0ull, q1 = 0ull, q2 = 0ull, q3 = 0ull;
            #pragma unroll
            for (int t = 0; t < 16; t += 2) {
                ulonglong2 cA = cp[t];
                ulonglong2 cB = cp[t + 1];
                asm("fma.rn.f32x2 %0, %1, %2, %0;" : "+l"(p0) : "l"(xp0[2 * t + 0]), "l"(cA.x));
                asm("fma.rn.f32x2 %0, %1, %2, %0;" : "+l"(q0) : "l"(xp1[2 * t + 0]), "l"(cA.x));
                asm("fma.rn.f32x2 %0, %1, %2, %0;" : "+l"(p1) : "l"(xp0[2 * t + 1]), "l"(cA.y));
                asm("fma.rn.f32x2 %0, %1, %2, %0;" : "+l"(q1) : "l"(xp1[2 * t + 1]), "l"(cA.y));
                asm("fma.rn.f32x2 %0, %1, %2, %0;" : "+l"(p2) : "l"(xp0[2 * t + 2]), "l"(cB.x));
                asm("fma.rn.f32x2 %0, %1, %2, %0;" : "+l"(q2) : "l"(xp1[2 * t + 2]), "l"(cB.x));
                asm("fma.rn.f32x2 %0, %1, %2, %0;" : "+l"(p3) : "l"(xp0[2 * t + 3]), "l"(cB.y));
                asm("fma.rn.f32x2 %0, %1, %2, %0;" : "+l"(q3) : "l"(xp1[2 * t + 3]), "l"(cB.y));
            }
            unsigned long long u01, u23, uu, v01, v23, vv;
            asm("add.rn.f32x2 %0, %1, %2;" : "=l"(u01) : "l"(p0), "l"(p1));
            asm("add.rn.f32x2 %0, %1, %2;" : "=l"(u23) : "l"(p2), "l"(p3));
            asm("add.rn.f32x2 %0, %1, %2;" : "=l"(uu)  : "l"(u01), "l"(u23));
            asm("add.rn.f32x2 %0, %1, %2;" : "=l"(v01) : "l"(q0), "l"(q1));
            asm("add.rn.f32x2 %0, %1, %2;" : "=l"(v23) : "l"(q2), "l"(q3));
            asm("add.rn.f32x2 %0, %1, %2;" : "=l"(vv)  : "l"(v01), "l"(v23));
            float lo0, hi0, lo1, hi1;
            asm("mov.b64 {%0, %1}, %2;" : "=f"(lo0), "=f"(hi0) : "l"(uu));
            asm("mov.b64 {%0, %1}, %2;" : "=f"(lo1), "=f"(hi1) : "l"(vv));
            float dot0 = lo0 + hi0;
            float dot1 = lo1 + hi1;
            float cs = s_csq[j];
            // faithful: (|x|^2 + |c|^2) - 2*dot, no FMA contraction
            float d0 = __fsub_rn(__fadd_rn(xsq0, cs), __fmul_rn(2.0f, dot0));
            float d1 = __fsub_rn(__fadd_rn(xsq1, cs), __fmul_rn(2.0f, dot1));
            if (d0 < best0) { best0 = d0; bj0 = c0i + j; }   // strict < = first-min
            if (d1 < best1) { best1 = d1; bj1 = c0i + j; }
        }
    }

    g_cd[q * NTOK + n0] = best0;  g_ci[q * NTOK + n0] = bj0;
    g_cd[q * NTOK + n1] = best1;  g_ci[q * NTOK + n1] = bj1;
}

// ---------------- K2: merge quarters + quantized + mse + histogram ----------
__global__ void __launch_bounds__(128) k_fin(const float* __restrict__ x,
                                             const float* __restrict__ cb,
                                             float* __restrict__ out) {
    const int tid = threadIdx.x;
    const int n   = blockIdx.x * 128 + tid;
    const int b   = n >> 10, hw = n & 1023;

    __shared__ int s_hist[KCB];
    #pragma unroll
    for (int k = 0; k < 8; k++) s_hist[tid + 128 * k] = 0;

    // merge in quarter order: strict < keeps earliest quarter => first-min over K
    float best = g_cd[n];
    int bestj  = g_ci[n];
    #pragma unroll
    for (int qq = 1; qq < NQ; qq++) {
        float d = g_cd[qq * NTOK + n];
        int   i = g_ci[qq * NTOK + n];
        if (d < best) { best = d; bestj = i; }
    }

    __syncthreads();
    atomicAdd(&s_hist[bestj], 1);

    // quantized output + mse
    const float* xb = x + (size_t)b * (DIM * HWSZ) + hw;
    const float4* q4 = (const float4*)(cb + (size_t)bestj * DIM);
    float* ob = out + (size_t)b * (DIM * HWSZ) + hw;
    float ms = 0.0f;
    #pragma unroll
    for (int t = 0; t < 16; t++) {
        float4 qv = __ldg(q4 + t);
        float x0 = xb[(4 * t + 0) * HWSZ];
        float x1 = xb[(4 * t + 1) * HWSZ];
        float x2 = xb[(4 * t + 2) * HWSZ];
        float x3 = xb[(4 * t + 3) * HWSZ];
        float d0 = __fsub_rn(qv.x, x0), d1 = __fsub_rn(qv.y, x1);
        float d2 = __fsub_rn(qv.z, x2), d3 = __fsub_rn(qv.w, x3);
        ms = fmaf(d0, d0, ms); ms = fmaf(d1, d1, ms);
        ms = fmaf(d2, d2, ms); ms = fmaf(d3, d3, ms);
        ob[(4 * t + 0) * HWSZ] = __fadd_rn(x0, d0);
        ob[(4 * t + 1) * HWSZ] = __fadd_rn(x1, d1);
        ob[(4 * t + 2) * HWSZ] = __fadd_rn(x2, d2);
        ob[(4 * t + 3) * HWSZ] = __fadd_rn(x3, d3);
    }
    #pragma unroll
    for (int o = 16; o > 0; o >>= 1) ms += __shfl_xor_sync(0xffffffffu, ms, o);
    __shared__ float s_ms[4];
    if ((tid & 31) == 0) s_ms[tid >> 5] = ms;
    __syncthreads();
    if (tid == 0) g_msepart[blockIdx.x] = (s_ms[0] + s_ms[1]) + (s_ms[2] + s_ms[3]);

    // sparse histogram flush (int atomics: deterministic)
    #pragma unroll
    for (int k = 0; k < 8; k++) {
        int v = s_hist[tid + 128 * k];
        if (v) atomicAdd(&g_hist[tid + 128 * k], v);
    }
}

// ---------------- block-wide sum (1024 threads) -----------------------------
__device__ __forceinline__ float bsum(float v, float* sh32, int tid) {
    #pragma unroll
    for (int o = 16; o > 0; o >>= 1) v += __shfl_xor_sync(0xffffffffu, v, o);
    if ((tid & 31) == 0) sh32[tid >> 5] = v;
    __syncthreads();
    if (tid < 32) {
        float w = sh32[tid];
        #pragma unroll
        for (int o = 16; o > 0; o >>= 1) w += __shfl_xor_sync(0xffffffffu, w, o);
        if (tid == 0) sh32[0] = w;
    }
    __syncthreads();
    float r = sh32[0];
    __syncthreads();
    return r;
}

// ---------------- K3: target + stats + OT dual + loss (one CTA) -------------
__global__ void __launch_bounds__(1024) k_ot(float* __restrict__ out) {
    const int j = threadIdx.x;
    __shared__ float sh32[32];
    __shared__ float s_lt[KCB];
    __shared__ float s_phi[KCB];
    __shared__ float s_lse[KCB];
    __shared__ float s_src[KCB];

    // consume histogram, restore load-time-zero invariant for next replay
    const int hj = g_hist[j];
    g_hist[j] = 0;

    // gaussian target (faithful: _gaussian_target then _norm_prob)
    float z = ((float)j - 511.5f) / (1024.0f / 6.0f);
    float t = expf(-0.5f * z * z);
    float sum1 = bsum(t, sh32, j);
    float t1 = t / fmaxf(sum1, 1e-12f);
    float t2 = fmaxf(t1, 1e-12f);
    float sum2 = bsum(t2, sh32, j);
    const float tgt = t2 / sum2;
    const float lt  = logf(fmaxf(tgt, 1e-12f));
    s_lt[j] = lt;

    // perplexity
    float avg = (float)hj / (float)NTOK;
    float ent = bsum(avg * logf(avg + 1e-10f), sh32, j);
    if (j == 0) out[QELEMS + 1] = expf(-ent);

    // src weights: norm_prob(hard_hist), then norm_prob again (dual_obj)
    float p1 = fmaxf(avg, 1e-12f);
    float s1 = bsum(p1, sh32, j);
    float p2 = fmaxf(p1 / s1, 1e-12f);
    float s2 = bsum(p2, sh32, j);
    const float src = p2 / s2;
    s_src[j] = src;

    // total mse
    const float mse_tot = bsum((j < NFIN) ? g_msepart[j] : 0.0f, sh32, j);

    // dual ascent loop (compile-time +/-WIN stencil)
    float phi = 0.0f;
    s_phi[j] = 0.0f;
    __syncthreads();

    float lse = 0.0f;
    for (int step = 0; step <= NSTEPS; step++) {
        float a[2 * WIN + 1];
        float m = -3.4e38f;
        #pragma unroll
        for (int u = -WIN; u <= WIN; u++) {
            int jj = j + u;
            bool valid = (jj >= 0) && (jj < KCB);
            int jc = valid ? jj : j;
            float v = s_lt[jc] + fmaf(s_phi[jc], INVEPS, -(float)(u < 0 ? -u : u) * INVEPS);
            v = valid ? v : -3.0e38f;
            a[u + WIN] = v;
            m = fmaxf(m, v);
        }
        float s = 0.0f;
        #pragma unroll
        for (int u = 0; u < 2 * WIN + 1; u++) s += expf(a[u] - m);
        lse = m + logf(s);
        s_lse[j] = lse;
        __syncthreads();
        if (step == NSTEPS) break;
        float mar = 0.0f;
        #pragma unroll
        for (int u = -WIN; u <= WIN; u++) {
            int i = j + u;
            bool valid = (i >= 0) && (i < KCB);
            int ic = valid ? i : j;
            float v = lt + fmaf(phi, INVEPS, -(float)(u < 0 ? -u : u) * INVEPS) - s_lse[ic];
            float c = s_src[ic] * expf(v);
            mar += valid ? c : 0.0f;
        }
        phi = phi + 0.5f * (tgt - mar);
        __syncthreads();
        s_phi[j] = phi;
        __syncthreads();
    }

    // dual objective + loss
    float t1s = bsum(src * (-0.05f * lse), sh32, j);
    float t2s = bsum(tgt * phi, sh32, j);
    if (j == 0) {
        float obj = t1s + t2s;                        // ot_loss (OT_W = 1)
        float m = mse_tot / (float)QELEMS;            // codebook == commit value
        out[QELEMS] = (m + 0.25f * m) + obj;          // loss
    }
}

// ---------------- launch ----------------------------------------------------
extern "C" void kernel_launch(void* const* d_in, const int* in_sizes, int n_in,
                              void* d_out, int out_size) {
    const float* x  = (const float*)d_in[0];   // inputs [32,64,32,32]
    const float* cb = (const float*)d_in[1];   // codebook [1024,64]
    if (n_in >= 2 && in_sizes[0] == KCB * DIM && in_sizes[1] == QELEMS) {
        x = (const float*)d_in[1]; cb = (const float*)d_in[0];
    }
    float* out = (float*)d_out;

    k_main<<<128 * NQ, 128>>>(x, cb);
    k_fin<<<NFIN, 128>>>(x, cb, out);
    k_ot<<<1, 1024>>>(out);
}

// round 13
// speedup vs baseline: 1.2004x; 1.0286x over previous
#include <cuda_runtime.h>
#include <math.h>

// Problem constants
#define NTOK   32768      // B*H*W
#define KCB    1024
#define DIM    64
#define HWSZ   1024
#define QELEMS 2097152    // NTOK*DIM
#define INVEPS 20.0f
#define NSTEPS 10
#define NFIN   256        // mse partials (one per CTA)
#define WIN    3          // OT stencil half-width (validated: identical to exact)

// ---------------- scratch (device globals) ----------------------------------
__device__ int   g_hist[KCB];         // zero at load; k_ot re-zeroes after use
__device__ float g_msepart[NFIN];

// ---------------- K1: register-tiled distance GEMM + argmin + epilogue ------
// 256 CTAs x 256 thr. Block tile 128 tokens x 128 codes; thread tile 8x8.
// x-tile loaded once per CTA; codebook streamed in 8 transposed chunks.
// Argmin via u64 atomicMin (d>0, so float bits order == numeric order; low
// bits = code index => exact first-min tie-break, deterministic).
__global__ void __launch_bounds__(256, 2) k_dist(const float* __restrict__ x,
                                                 const float* __restrict__ cb,
                                                 float* __restrict__ out) {
    const int tid  = threadIdx.x;
    const int tok0 = blockIdx.x * 128;
    const int b    = tok0 >> 10;
    const int hw0  = tok0 & 1023;

    __shared__ float s_x[DIM * 128];     // [d][tok]  32 KB
    __shared__ float s_c[DIM * 128];     // [d][code] 32 KB (transposed chunk)
    __shared__ float s_xsq[128];
    __shared__ float s_csq[128];
    __shared__ unsigned long long s_best[128];

    // ---- load x tile (coalesced float4, conflict-free STS.128) ----
    const float* xbase = x + (size_t)b * (DIM * HWSZ) + hw0;
    #pragma unroll
    for (int i = 0; i < 8; i++) {
        int idx = i * 256 + tid;          // 0..2047
        int d   = idx >> 5;               // 0..63
        int t4  = idx & 31;               // float4 col
        float4 v = __ldg((const float4*)(xbase + (size_t)d * HWSZ) + t4);
        *(float4*)(s_x + d * 128 + 4 * t4) = v;
    }
    if (tid < 128) s_best[tid] = 0xFFFFFFFFFFFFFFFFull;
    __syncthreads();

    // ---- |x|^2 per token (sequential dims: deterministic, faithful chain) --
    if (tid < 128) {
        float s = 0.0f;
        #pragma unroll 8
        for (int d = 0; d < DIM; d++) { float v = s_x[d * 128 + tid]; s = fmaf(v, v, s); }
        s_xsq[tid] = s;
    }
    __syncthreads();

    const int tm = tid & 15;              // token group: tokens tm*8..+8
    const int cn = tid >> 4;              // code group:  codes  cn*8..+8
    float xsq8[8];
    #pragma unroll
    for (int t = 0; t < 8; t++) xsq8[t] = s_xsq[tm * 8 + t];

    float best[8];
    int   bidx[8];
    #pragma unroll
    for (int t = 0; t < 8; t++) { best[t] = 3.4e38f; bidx[t] = 0; }

    for (int chunk = 0; chunk < 8; chunk++) {
        __syncthreads();
        // ---- transpose 128 codes into s_c[d][code]; lane<->code => STS
        // bank = code mod 32, conflict-free ----
        {
            int code = tid & 127;
            int half = tid >> 7;          // dims split across 2 threads/code
            const float4* crow = (const float4*)(cb + (size_t)(chunk * 128 + code) * DIM);
            #pragma unroll
            for (int i = 0; i < 8; i++) {
                int g = half * 8 + i;     // float4 group 0..15
                float4 v = __ldg(crow + g);
                s_c[(4 * g + 0) * 128 + code] = v.x;
                s_c[(4 * g + 1) * 128 + code] = v.y;
                s_c[(4 * g + 2) * 128 + code] = v.z;
                s_c[(4 * g + 3) * 128 + code] = v.w;
            }
        }
        __syncthreads();
        // ---- |c|^2 per code (sequential dims) ----
        if (tid < 128) {
            float s = 0.0f;
            #pragma unroll 8
            for (int d = 0; d < DIM; d++) { float v = s_c[d * 128 + tid]; s = fmaf(v, v, s); }
            s_csq[tid] = s;
        }
        __syncthreads();

        // ---- 8x8 register-tile dot products, FMA2 over token pairs ----
        unsigned long long acc[4][8];
        #pragma unroll
        for (int tp = 0; tp < 4; tp++)
            #pragma unroll
            for (int c = 0; c < 8; c++) acc[tp][c] = 0ull;

        #pragma unroll 2
        for (int k = 0; k < DIM; k++) {
            float4 xa = *(const float4*)(s_x + k * 128 + tm * 8);
            float4 xbv = *(const float4*)(s_x + k * 128 + tm * 8 + 4);
            unsigned long long xp[4];
            asm("mov.b64 %0, {%1, %2};" : "=l"(xp[0]) : "f"(xa.x),  "f"(xa.y));
            asm("mov.b64 %0, {%1, %2};" : "=l"(xp[1]) : "f"(xa.z),  "f"(xa.w));
            asm("mov.b64 %0, {%1, %2};" : "=l"(xp[2]) : "f"(xbv.x), "f"(xbv.y));
            asm("mov.b64 %0, {%1, %2};" : "=l"(xp[3]) : "f"(xbv.z), "f"(xbv.w));
            float4 ca = *(const float4*)(s_c + k * 128 + cn * 8);
            float4 cbv = *(const float4*)(s_c + k * 128 + cn * 8 + 4);
            unsigned long long cd[8];
            asm("mov.b64 %0, {%1, %1};" : "=l"(cd[0]) : "f"(ca.x));
            asm("mov.b64 %0, {%1, %1};" : "=l"(cd[1]) : "f"(ca.y));
            asm("mov.b64 %0, {%1, %1};" : "=l"(cd[2]) : "f"(ca.z));
            asm("mov.b64 %0, {%1, %1};" : "=l"(cd[3]) : "f"(ca.w));
            asm("mov.b64 %0, {%1, %1};" : "=l"(cd[4]) : "f"(cbv.x));
            asm("mov.b64 %0, {%1, %1};" : "=l"(cd[5]) : "f"(cbv.y));
            asm("mov.b64 %0, {%1, %1};" : "=l"(cd[6]) : "f"(cbv.z));
            asm("mov.b64 %0, {%1, %1};" : "=l"(cd[7]) : "f"(cbv.w));
            #pragma unroll
            for (int c = 0; c < 8; c++) {
                asm("fma.rn.f32x2 %0, %1, %2, %0;" : "+l"(acc[0][c]) : "l"(xp[0]), "l"(cd[c]));
                asm("fma.rn.f32x2 %0, %1, %2, %0;" : "+l"(acc[1][c]) : "l"(xp[1]), "l"(cd[c]));
                asm("fma.rn.f32x2 %0, %1, %2, %0;" : "+l"(acc[2][c]) : "l"(xp[2]), "l"(cd[c]));
                asm("fma.rn.f32x2 %0, %1, %2, %0;" : "+l"(acc[3][c]) : "l"(xp[3]), "l"(cd[c]));
            }
        }

        // ---- distances + running argmin (ascending code order) ----
        #pragma unroll
        for (int c = 0; c < 8; c++) {
            float cs = s_csq[cn * 8 + c];
            int gcode = chunk * 128 + cn * 8 + c;
            #pragma unroll
            for (int tp = 0; tp < 4; tp++) {
                float d0, d1;
                asm("mov.b64 {%0, %1}, %2;" : "=f"(d0), "=f"(d1) : "l"(acc[tp][c]));
                // faithful: (|x|^2 + |c|^2) - 2*dot, no FMA contraction
                float dist0 = __fsub_rn(__fadd_rn(xsq8[2 * tp],     cs), __fmul_rn(2.0f, d0));
                float dist1 = __fsub_rn(__fadd_rn(xsq8[2 * tp + 1], cs), __fmul_rn(2.0f, d1));
                if (dist0 < best[2 * tp])     { best[2 * tp]     = dist0; bidx[2 * tp]     = gcode; }
                if (dist1 < best[2 * tp + 1]) { best[2 * tp + 1] = dist1; bidx[2 * tp + 1] = gcode; }
            }
        }
    }

    // ---- cross-thread argmin: u64 atomicMin, index tie-break = first-min ---
    #pragma unroll
    for (int t = 0; t < 8; t++) {
        unsigned long long key =
            ((unsigned long long)__float_as_uint(best[t]) << 32) | (unsigned)bidx[t];
        atomicMin(&s_best[tm * 8 + t], key);
    }
    __syncthreads();

    // ---- epilogue: quantized out + mse + histogram (token-owner threads) ---
    float ms = 0.0f;
    if (tid < 128) {
        int tok = tid;
        int bj  = (int)(s_best[tok] & 0xFFFFFFFFull);
        atomicAdd(&g_hist[bj], 1);
        const float4* q4 = (const float4*)(cb + (size_t)bj * DIM);
        float* ob = out + (size_t)b * (DIM * HWSZ) + hw0 + tok;
        #pragma unroll
        for (int t = 0; t < 16; t++) {
            float4 qv = __ldg(q4 + t);
            float x0 = s_x[(4 * t + 0) * 128 + tok];
            float x1 = s_x[(4 * t + 1) * 128 + tok];
            float x2 = s_x[(4 * t + 2) * 128 + tok];
            float x3 = s_x[(4 * t + 3) * 128 + tok];
            float d0 = __fsub_rn(qv.x, x0), d1 = __fsub_rn(qv.y, x1);
            float d2 = __fsub_rn(qv.z, x2), d3 = __fsub_rn(qv.w, x3);
            ms = fmaf(d0, d0, ms); ms = fmaf(d1, d1, ms);
            ms = fmaf(d2, d2, ms); ms = fmaf(d3, d3, ms);
            ob[(4 * t + 0) * HWSZ] = __fadd_rn(x0, d0);
            ob[(4 * t + 1) * HWSZ] = __fadd_rn(x1, d1);
            ob[(4 * t + 2) * HWSZ] = __fadd_rn(x2, d2);
            ob[(4 * t + 3) * HWSZ] = __fadd_rn(x3, d3);
        }
    }
    // mse reduce over the 4 active warps (identical tree to prior rounds)
    if (tid < 128) {
        #pragma unroll
        for (int o = 16; o > 0; o >>= 1) ms += __shfl_xor_sync(0xffffffffu, ms, o);
        __shared__ float s_ms[4];
        if ((tid & 31) == 0) s_ms[tid >> 5] = ms;
        __syncthreads();
        if (tid == 0) g_msepart[blockIdx.x] = (s_ms[0] + s_ms[1]) + (s_ms[2] + s_ms[3]);
    }
}

// ---------------- block-wide sum (1024 threads) -----------------------------
__device__ __forceinline__ float bsum(float v, float* sh32, int tid) {
    #pragma unroll
    for (int o = 16; o > 0; o >>= 1) v += __shfl_xor_sync(0xffffffffu, v, o);
    if ((tid & 31) == 0) sh32[tid >> 5] = v;
    __syncthreads();
    if (tid < 32) {
        float w = sh32[tid];
        #pragma unroll
        for (int o = 16; o > 0; o >>= 1) w += __shfl_xor_sync(0xffffffffu, w, o);
        if (tid == 0) sh32[0] = w;
    }
    __syncthreads();
    float r = sh32[0];
    __syncthreads();
    return r;
}

// ---------------- K2: target + stats + OT dual + loss (one CTA) -------------
__global__ void __launch_bounds__(1024) k_ot(float* __restrict__ out) {
    const int j = threadIdx.x;
    __shared__ float sh32[32];
    __shared__ float s_lt[KCB];
    __shared__ float s_phi[KCB];
    __shared__ float s_lse[KCB];
    __shared__ float s_src[KCB];

    // consume histogram, restore load-time-zero invariant for next replay
    const int hj = g_hist[j];
    g_hist[j] = 0;

    // gaussian target (faithful: _gaussian_target then _norm_prob)
    float z = ((float)j - 511.5f) / (1024.0f / 6.0f);
    float t = expf(-0.5f * z * z);
    float sum1 = bsum(t, sh32, j);
    float t1 = t / fmaxf(sum1, 1e-12f);
    float t2 = fmaxf(t1, 1e-12f);
    float sum2 = bsum(t2, sh32, j);
    const float tgt = t2 / sum2;
    const float lt  = logf(fmaxf(tgt, 1e-12f));
    s_lt[j] = lt;

    // perplexity
    float avg = (float)hj / (float)NTOK;
    float ent = bsum(avg * logf(avg + 1e-10f), sh32, j);
    if (j == 0) out[QELEMS + 1] = expf(-ent);

    // src weights: norm_prob(hard_hist), then norm_prob again (dual_obj)
    float p1 = fmaxf(avg, 1e-12f);
    float s1 = bsum(p1, sh32, j);
    float p2 = fmaxf(p1 / s1, 1e-12f);
    float s2 = bsum(p2, sh32, j);
    const float src = p2 / s2;
    s_src[j] = src;

    // total mse
    const float mse_tot = bsum((j < NFIN) ? g_msepart[j] : 0.0f, sh32, j);

    // dual ascent loop (compile-time +/-WIN stencil)
    float phi = 0.0f;
    s_phi[j] = 0.0f;
    __syncthreads();

    float lse = 0.0f;
    for (int step = 0; step <= NSTEPS; step++) {
        float a[2 * WIN + 1];
        float m = -3.4e38f;
        #pragma unroll
        for (int u = -WIN; u <= WIN; u++) {
            int jj = j + u;
            bool valid = (jj >= 0) && (jj < KCB);
            int jc = valid ? jj : j;
            float v = s_lt[jc] + fmaf(s_phi[jc], INVEPS, -(float)(u < 0 ? -u : u) * INVEPS);
            v = valid ? v : -3.0e38f;
            a[u + WIN] = v;
            m = fmaxf(m, v);
        }
        float s = 0.0f;
        #pragma unroll
        for (int u = 0; u < 2 * WIN + 1; u++) s += expf(a[u] - m);
        lse = m + logf(s);
        s_lse[j] = lse;
        __syncthreads();
        if (step == NSTEPS) break;
        float mar = 0.0f;
        #pragma unroll
        for (int u = -WIN; u <= WIN; u++) {
            int i = j + u;
            bool valid = (i >= 0) && (i < KCB);
            int ic = valid ? i : j;
            float v = lt + fmaf(phi, INVEPS, -(float)(u < 0 ? -u : u) * INVEPS) - s_lse[ic];
            float c = s_src[ic] * expf(v);
            mar += valid ? c : 0.0f;
        }
        phi = phi + 0.5f * (tgt - mar);
        __syncthreads();
        s_phi[j] = phi;
        __syncthreads();
    }

    // dual objective + loss
    float t1s = bsum(src * (-0.05f * lse), sh32, j);
    float t2s = bsum(tgt * phi, sh32, j);
    if (j == 0) {
        float obj = t1s + t2s;                        // ot_loss (OT_W = 1)
        float m = mse_tot / (float)QELEMS;            // codebook == commit value
        out[QELEMS] = (m + 0.25f * m) + obj;          // loss
    }
}

// ---------------- launch ----------------------------------------------------
extern "C" void kernel_launch(void* const* d_in, const int* in_sizes, int n_in,
                              void* d_out, int out_size) {
    const float* x  = (const float*)d_in[0];   // inputs [32,64,32,32]
    const float* cb = (const float*)d_in[1];   // codebook [1024,64]
    if (n_in >= 2 && in_sizes[0] == KCB * DIM && in_sizes[1] == QELEMS) {
        x = (const float*)d_in[1]; cb = (const float*)d_in[0];
    }
    float* out = (float*)d_out;

    k_dist<<<NTOK / 128, 256>>>(x, cb, out);
    k_ot<<<1, 1024>>>(out);
}

// round 16
// speedup vs baseline: 1.7074x; 1.4224x over previous
#include <cuda_runtime.h>
#include <cuda_fp16.h>
#include <math.h>
#include <stdint.h>

// Problem constants
#define NTOK   32768
#define KCB    1024
#define DIM    64
#define HWSZ   1024
#define QELEMS 2097152
#define INVEPS 20.0f
#define NSTEPS 10
#define NFIN   256
#define WIN    3
#define PAD    36          // u32 stride per row (64 f16 = 32 words + 4 pad) -> conflict-free frags
#define CSCALE 1024.0f     // 2^10: lifts codebook (~1e-3) into normal fp16 range for the split
#define CINV   0.0009765625f  // 2^-10, exact

// ---------------- scratch (device globals) ----------------------------------
__device__ __half g_ch[KCB * DIM];    // fp16 hi of (codebook * 2^10)
__device__ __half g_cl[KCB * DIM];    // fp16 lo residual (normal-range now)
__device__ float  g_csq[KCB];         // |c|^2 in ORIGINAL units
__device__ int    g_hist[KCB];        // zero at load; k_ot re-zeroes after use
__device__ float  g_msepart[NFIN];

// ---------------- warp-level HMMA (portable mma.sync; compiles at sm_103) ---
__device__ __forceinline__ void mma16816(float& d0, float& d1, float& d2, float& d3,
                                         uint32_t a0, uint32_t a1, uint32_t a2, uint32_t a3,
                                         uint32_t b0, uint32_t b1) {
    asm volatile(
        "mma.sync.aligned.m16n8k16.row.col.f32.f16.f16.f32 "
        "{%0,%1,%2,%3}, {%4,%5,%6,%7}, {%8,%9}, {%0,%1,%2,%3};"
        : "+f"(d0), "+f"(d1), "+f"(d2), "+f"(d3)
        : "r"(a0), "r"(a1), "r"(a2), "r"(a3), "r"(b0), "r"(b1));
}

// ---------------- K0: split scaled codebook into fp16 hi/lo + |c|^2 ---------
__global__ void k_split(const float* __restrict__ cb) {
    int code = blockIdx.x * 128 + threadIdx.x;      // <<<8,128>>>
    const float4* r = (const float4*)(cb + (size_t)code * DIM);
    float s = 0.0f;
    #pragma unroll
    for (int t = 0; t < 16; t++) {
        float4 c = __ldg(r + t);
        s = fmaf(c.x, c.x, s); s = fmaf(c.y, c.y, s);
        s = fmaf(c.z, c.z, s); s = fmaf(c.w, c.w, s);
        #pragma unroll
        for (int e = 0; e < 4; e++) {
            float v = (e == 0) ? c.x : (e == 1) ? c.y : (e == 2) ? c.z : c.w;
            float vs = v * CSCALE;                 // exact (power of 2)
            __half h = __float2half_rn(vs);
            g_ch[code * DIM + 4 * t + e] = h;
            g_cl[code * DIM + 4 * t + e] = __float2half_rn(vs - __half2float(h));
        }
    }
    g_csq[code] = s;
}

// ---------------- K1: HMMA distance GEMM + argmin + epilogue ----------------
// 256 CTAs x 256 thr (8 warps). Warp w owns tokens w*16..w*16+15.
// dot' = xh*ch' + xh*cl' + xl*ch' in scaled space; dot = dot' * 2^-10 (exact).
// Total dot error ~2e-9 vs argmin gaps ~1e-6 (500x margin).
// Argmin keys: (float_bits(d)<<32)|code, d>0 => exact first-min w/ tie-break.
__global__ void __launch_bounds__(256, 2) k_dist(const float* __restrict__ x,
                                                 const float* __restrict__ cb,
                                                 float* __restrict__ out) {
    __shared__ uint32_t s_buf[2][128 * PAD];   // phase1: A(h,l); phase2: B(h,l). 36 KB
    __shared__ float s_xsq[128];
    __shared__ float s_csq[128];
    __shared__ unsigned long long s_best[128];

    const int tid  = threadIdx.x;
    const int wid  = tid >> 5;
    const int lane = tid & 31;
    const int gid  = lane >> 2;       // groupID (fragment row / B col)
    const int tid4 = lane & 3;        // threadID-in-group
    const int tok0 = blockIdx.x * 128;
    const int b    = tok0 >> 10;
    const int hw0  = tok0 & 1023;

    // ---- phase 1: token owners (tid<128) load x, split fp16, stage A -------
    const float* xb = x + (size_t)b * (DIM * HWSZ) + hw0 + (tid & 127);
    if (tid < 128) {
        float xsq = 0.0f;
        #pragma unroll
        for (int t = 0; t < 32; t++) {
            float e0 = xb[(2 * t) * HWSZ];
            float e1 = xb[(2 * t + 1) * HWSZ];
            xsq = fmaf(e0, e0, xsq);
            xsq = fmaf(e1, e1, xsq);
            __half h0 = __float2half_rn(e0), h1 = __float2half_rn(e1);
            __half l0 = __float2half_rn(e0 - __half2float(h0));
            __half l1 = __float2half_rn(e1 - __half2float(h1));
            __half2 ph = __halves2half2(h0, h1);
            __half2 pl = __halves2half2(l0, l1);
            s_buf[0][tid * PAD + t] = *(uint32_t*)&ph;
            s_buf[1][tid * PAD + t] = *(uint32_t*)&pl;
        }
        s_xsq[tid] = xsq;
    }
    __syncthreads();

    // ---- extract A fragments (per warp tile, register-resident) ------------
    // m16n8k16 A: reg0=(r,k0..1) reg1=(r+8,k0..1) reg2=(r,k8..9) reg3=(r+8,k8..9)
    uint32_t afr[2][4][4];   // [split][kslice][reg]
    {
        int r0 = wid * 16 + gid;
        #pragma unroll
        for (int sp = 0; sp < 2; sp++)
            #pragma unroll
            for (int ks = 0; ks < 4; ks++) {
                int base = ks * 8 + tid4;
                afr[sp][ks][0] = s_buf[sp][r0 * PAD + base];
                afr[sp][ks][1] = s_buf[sp][(r0 + 8) * PAD + base];
                afr[sp][ks][2] = s_buf[sp][r0 * PAD + base + 4];
                afr[sp][ks][3] = s_buf[sp][(r0 + 8) * PAD + base + 4];
            }
    }
    const float xsq_r  = s_xsq[wid * 16 + gid];
    const float xsq_r8 = s_xsq[wid * 16 + gid + 8];
    __syncthreads();   // A extracted; s_buf free for B chunks

    unsigned long long key_r  = 0xFFFFFFFFFFFFFFFFull;
    unsigned long long key_r8 = 0xFFFFFFFFFFFFFFFFull;

    for (int chunk = 0; chunk < 8; chunk++) {
        // ---- stage B chunk: 128 codes x 64 f16, hi+lo, padded stride -------
        {
            int code = tid & 127;
            int sp   = tid >> 7;
            const uint4* src = (const uint4*)((sp ? g_cl : g_ch) + (size_t)(chunk * 128 + code) * DIM);
            #pragma unroll
            for (int g = 0; g < 8; g++)
                *(uint4*)&s_buf[sp][code * PAD + g * 4] = __ldg(src + g);
            if (tid < 128) s_csq[tid] = g_csq[chunk * 128 + tid];
        }
        __syncthreads();

        #pragma unroll 2
        for (int nb = 0; nb < 16; nb++) {
            // B frags: reg0=(k 2*tid4..+1, col gid) reg1=(k+8), per kslice/split
            const int bc = (nb * 8 + gid) * PAD;
            float d0 = 0.f, d1 = 0.f, d2 = 0.f, d3 = 0.f;
            #pragma unroll
            for (int ks = 0; ks < 4; ks++) {      // xh * ch'
                uint32_t b0 = s_buf[0][bc + ks * 8 + tid4];
                uint32_t b1 = s_buf[0][bc + ks * 8 + tid4 + 4];
                mma16816(d0, d1, d2, d3, afr[0][ks][0], afr[0][ks][1], afr[0][ks][2], afr[0][ks][3], b0, b1);
            }
            #pragma unroll
            for (int ks = 0; ks < 4; ks++) {      // xh * cl'
                uint32_t b0 = s_buf[1][bc + ks * 8 + tid4];
                uint32_t b1 = s_buf[1][bc + ks * 8 + tid4 + 4];
                mma16816(d0, d1, d2, d3, afr[0][ks][0], afr[0][ks][1], afr[0][ks][2], afr[0][ks][3], b0, b1);
            }
            #pragma unroll
            for (int ks = 0; ks < 4; ks++) {      // xl * ch'
                uint32_t b0 = s_buf[0][bc + ks * 8 + tid4];
                uint32_t b1 = s_buf[0][bc + ks * 8 + tid4 + 4];
                mma16816(d0, d1, d2, d3, afr[1][ks][0], afr[1][ks][1], afr[1][ks][2], afr[1][ks][3], b0, b1);
            }
            // unscale (exact power-of-2 multiply)
            float u0 = d0 * CINV, u1 = d1 * CINV, u2 = d2 * CINV, u3 = d3 * CINV;
            // D: c0=(r,2tid4) c1=(r,2tid4+1) c2=(r+8,2tid4) c3=(r+8,2tid4+1)
            float2 cs = *(const float2*)&s_csq[nb * 8 + 2 * tid4];
            int gc0 = chunk * 128 + nb * 8 + 2 * tid4;
            // faithful: (|x|^2 + |c|^2) - 2*dot, no FMA contraction
            float e0 = __fsub_rn(__fadd_rn(xsq_r,  cs.x), __fmul_rn(2.0f, u0));
            float e1 = __fsub_rn(__fadd_rn(xsq_r,  cs.y), __fmul_rn(2.0f, u1));
            float e2 = __fsub_rn(__fadd_rn(xsq_r8, cs.x), __fmul_rn(2.0f, u2));
            float e3 = __fsub_rn(__fadd_rn(xsq_r8, cs.y), __fmul_rn(2.0f, u3));
            unsigned long long k0 = ((unsigned long long)__float_as_uint(e0) << 32) | (unsigned)gc0;
            unsigned long long k1 = ((unsigned long long)__float_as_uint(e1) << 32) | (unsigned)(gc0 + 1);
            unsigned long long k2 = ((unsigned long long)__float_as_uint(e2) << 32) | (unsigned)gc0;
            unsigned long long k3 = ((unsigned long long)__float_as_uint(e3) << 32) | (unsigned)(gc0 + 1);
            key_r  = min(key_r,  min(k0, k1));
            key_r8 = min(key_r8, min(k2, k3));
        }
        __syncthreads();
    }

    // ---- quad reduce (lanes sharing a row) + publish ----
    key_r  = min(key_r,  __shfl_xor_sync(0xffffffffu, key_r, 1));
    key_r  = min(key_r,  __shfl_xor_sync(0xffffffffu, key_r, 2));
    key_r8 = min(key_r8, __shfl_xor_sync(0xffffffffu, key_r8, 1));
    key_r8 = min(key_r8, __shfl_xor_sync(0xffffffffu, key_r8, 2));
    if (tid4 == 0) {
        s_best[wid * 16 + gid]     = key_r;
        s_best[wid * 16 + gid + 8] = key_r8;
    }
    __syncthreads();

    // ---- epilogue: quantized out + mse + histogram (thread = token) ----
    float ms = 0.0f;
    if (tid < 128) {
        int bidx = (int)(s_best[tid] & 0xFFFFFFFFull);
        atomicAdd(&g_hist[bidx], 1);
        const float4* q4 = (const float4*)(cb + (size_t)bidx * DIM);
        float* ob = out + (size_t)b * (DIM * HWSZ) + hw0 + tid;
        #pragma unroll
        for (int t = 0; t < 16; t++) {
            float4 qv = __ldg(q4 + t);
            float x0 = xb[(4 * t + 0) * HWSZ];
            float x1 = xb[(4 * t + 1) * HWSZ];
            float x2 = xb[(4 * t + 2) * HWSZ];
            float x3 = xb[(4 * t + 3) * HWSZ];
            float f0 = __fsub_rn(qv.x, x0), f1 = __fsub_rn(qv.y, x1);
            float f2 = __fsub_rn(qv.z, x2), f3 = __fsub_rn(qv.w, x3);
            ms = fmaf(f0, f0, ms); ms = fmaf(f1, f1, ms);
            ms = fmaf(f2, f2, ms); ms = fmaf(f3, f3, ms);
            ob[(4 * t + 0) * HWSZ] = __fadd_rn(x0, f0);
            ob[(4 * t + 1) * HWSZ] = __fadd_rn(x1, f1);
            ob[(4 * t + 2) * HWSZ] = __fadd_rn(x2, f2);
            ob[(4 * t + 3) * HWSZ] = __fadd_rn(x3, f3);
        }
        #pragma unroll
        for (int o = 16; o > 0; o >>= 1) ms += __shfl_xor_sync(0xffffffffu, ms, o);
        __shared__ float s_ms[4];
        if ((tid & 31) == 0) s_ms[wid] = ms;
        __syncthreads();
        if (tid == 0) g_msepart[blockIdx.x] = (s_ms[0] + s_ms[1]) + (s_ms[2] + s_ms[3]);
    }
}

// ---------------- block-wide sum (1024 threads) -----------------------------
__device__ __forceinline__ float bsum(float v, float* sh32, int tid) {
    #pragma unroll
    for (int o = 16; o > 0; o >>= 1) v += __shfl_xor_sync(0xffffffffu, v, o);
    if ((tid & 31) == 0) sh32[tid >> 5] = v;
    __syncthreads();
    if (tid < 32) {
        float w = sh32[tid];
        #pragma unroll
        for (int o = 16; o > 0; o >>= 1) w += __shfl_xor_sync(0xffffffffu, w, o);
        if (tid == 0) sh32[0] = w;
    }
    __syncthreads();
    float r = sh32[0];
    __syncthreads();
    return r;
}

// ---------------- K2: target + stats + OT dual + loss (one CTA) -------------
__global__ void __launch_bounds__(1024) k_ot(float* __restrict__ out) {
    const int j = threadIdx.x;
    __shared__ float sh32[32];
    __shared__ float s_lt[KCB];
    __shared__ float s_phi[KCB];
    __shared__ float s_lse[KCB];
    __shared__ float s_src[KCB];

    const int hj = g_hist[j];
    g_hist[j] = 0;                          // restore zero invariant per replay

    // gaussian target (faithful: _gaussian_target then _norm_prob)
    float z = ((float)j - 511.5f) / (1024.0f / 6.0f);
    float t = expf(-0.5f * z * z);
    float sum1 = bsum(t, sh32, j);
    float t1 = t / fmaxf(sum1, 1e-12f);
    float t2 = fmaxf(t1, 1e-12f);
    float sum2 = bsum(t2, sh32, j);
    const float tgt = t2 / sum2;
    const float lt  = logf(fmaxf(tgt, 1e-12f));
    s_lt[j] = lt;

    // perplexity
    float avg = (float)hj / (float)NTOK;
    float ent = bsum(avg * logf(avg + 1e-10f), sh32, j);
    if (j == 0) out[QELEMS + 1] = expf(-ent);

    // src weights: norm_prob(hard_hist), then norm_prob again (dual_obj)
    float p1 = fmaxf(avg, 1e-12f);
    float s1 = bsum(p1, sh32, j);
    float p2 = fmaxf(p1 / s1, 1e-12f);
    float s2 = bsum(p2, sh32, j);
    const float src = p2 / s2;
    s_src[j] = src;

    // total mse
    const float mse_tot = bsum((j < NFIN) ? g_msepart[j] : 0.0f, sh32, j);

    // dual ascent loop (compile-time +/-WIN stencil; fast exp/log: rel err
    // ~1e-6 on lse/phi, far below the 1e-3 tolerance)
    float phi = 0.0f;
    s_phi[j] = 0.0f;
    __syncthreads();

    float lse = 0.0f;
    for (int step = 0; step <= NSTEPS; step++) {
        float a[2 * WIN + 1];
        float m = -3.4e38f;
        #pragma unroll
        for (int u = -WIN; u <= WIN; u++) {
            int jj = j + u;
            bool valid = (jj >= 0) && (jj < KCB);
            int jc = valid ? jj : j;
            float v = s_lt[jc] + fmaf(s_phi[jc], INVEPS, -(float)(u < 0 ? -u : u) * INVEPS);
            v = valid ? v : -3.0e38f;
            a[u + WIN] = v;
            m = fmaxf(m, v);
        }
        float s = 0.0f;
        #pragma unroll
        for (int u = 0; u < 2 * WIN + 1; u++) s += __expf(a[u] - m);
        lse = m + __logf(s);
        s_lse[j] = lse;
        __syncthreads();
        if (step == NSTEPS) break;
        float mar = 0.0f;
        #pragma unroll
        for (int u = -WIN; u <= WIN; u++) {
            int i = j + u;
            bool valid = (i >= 0) && (i < KCB);
            int ic = valid ? i : j;
            float v = lt + fmaf(phi, INVEPS, -(float)(u < 0 ? -u : u) * INVEPS) - s_lse[ic];
            float c = s_src[ic] * __expf(v);
            mar += valid ? c : 0.0f;
        }
        phi = phi + 0.5f * (tgt - mar);
        __syncthreads();
        s_phi[j] = phi;
        __syncthreads();
    }

    // dual objective + loss
    float t1s = bsum(src * (-0.05f * lse), sh32, j);
    float t2s = bsum(tgt * phi, sh32, j);
    if (j == 0) {
        float obj = t1s + t2s;                        // ot_loss (OT_W = 1)
        float m = mse_tot / (float)QELEMS;            // codebook == commit value
        out[QELEMS] = (m + 0.25f * m) + obj;          // loss
    }
}

// ---------------- launch ----------------------------------------------------
extern "C" void kernel_launch(void* const* d_in, const int* in_sizes, int n_in,
                              void* d_out, int out_size) {
    const float* x  = (const float*)d_in[0];   // inputs [32,64,32,32]
    const float* cb = (const float*)d_in[1];   // codebook [1024,64]
    if (n_in >= 2 && in_sizes[0] == KCB * DIM && in_sizes[1] == QELEMS) {
        x = (const float*)d_in[1]; cb = (const float*)d_in[0];
    }
    float* out = (float*)d_out;

    k_split<<<8, 128>>>(cb);
    k_dist<<<NTOK / 128, 256>>>(x, cb, out);
    k_ot<<<1, 1024>>>(out);
}